// round 16
// baseline (speedup 1.0000x reference)
#include <cuda_runtime.h>
#include <cuda_bf16.h>
#include <cuda_fp16.h>

// Problem constants (fixed by the dataset)
#define NN 100000
#define EE 1600000
#define HH 32
#define NTILE 98                       // ceil(NN / 1024)

#define CDIV(a, b) (((a) + (b) - 1) / (b))

// Scratch (static device globals; no allocation allowed)
__device__ int      g_deg[NN];         // zero at entry (reset each call in phase C)
__device__ int      g_rank[EE];        // within-dst-bucket rank of each edge
__device__ int      g_rowptr[NN + 1];
__device__ int      g_blocksums[NTILE];
__device__ float    g_dinv[NN];
__device__ int      g_csri[EE];        // src indices, bucketed by dst
__device__ __half   g_t0[NN * HH];     // t ping (fp16, pre-scaled by dinv[src])
__device__ __half   g_t1[NN * HH];     // t pong
__device__ unsigned g_bar_arrive;      // grid barrier state
__device__ unsigned g_bar_gen;

// Device-side buffer selection (NEVER pass __device__ globals from host!)
__device__ __forceinline__ __half* tbuf(int s) { return s ? g_t1 : g_t0; }

// ---------------------------------------------------------------------------
// Software grid barrier (all blocks resident by construction).
// ---------------------------------------------------------------------------
__device__ __forceinline__ void gsync() {
    __threadfence();
    __syncthreads();
    if (threadIdx.x == 0) {
        unsigned gen = *(volatile unsigned*)&g_bar_gen;
        unsigned rank = atomicAdd(&g_bar_arrive, 1u);
        if (rank == gridDim.x - 1) {
            g_bar_arrive = 0;
            __threadfence();
            atomicExch(&g_bar_gen, gen + 1u);
        } else {
            while (*(volatile unsigned*)&g_bar_gen == gen) { __nanosleep(64); }
        }
    }
    __syncthreads();
    __threadfence();
}

// Pack two floats into one fp16x2 word (scalar reinterpret; stays in regs).
__device__ __forceinline__ unsigned pk(float x, float y) {
    __half2 h = __float22half2_rn(make_float2(x, y));
    return *reinterpret_cast<unsigned*>(&h);
}

// ---------------------------------------------------------------------------
// Persistent kernel: CSR build (deg+rank -> tile scan -> finalize -> fill)
// and encoder+xform1, with the fill and encoder phases overlapped (no barrier
// between them: disjoint outputs). Gathers stay standalone (need full
// occupancy; CSR/enc phases are throughput-bound and occupancy-insensitive).
// smem layout: [0:3360) encoder weights (persist to last phase),
//              [3360:3616) scan scratch ints.
// ---------------------------------------------------------------------------
__global__ void csr_enc_kernel(const float* __restrict__ x, const float* __restrict__ y,
                               const int* __restrict__ src, const int* __restrict__ dst,
                               const int* __restrict__ bidx, const int* __restrict__ iidx,
                               int NB,
                               const float* __restrict__ Wb1, const float* __restrict__ bb1,
                               const float* __restrict__ Wb2, const float* __restrict__ bb2,
                               const float* __restrict__ Wi1, const float* __restrict__ bi1,
                               const float* __restrict__ Wi2, const float* __restrict__ bi2,
                               const float* __restrict__ Wc1) {
    __shared__ float smem[3616];
    int* sInt = (int*)(smem + 3360);
    int tid = threadIdx.x;
    int gid = blockIdx.x * blockDim.x + tid;
    int stride = gridDim.x * blockDim.x;

    // Load encoder + Wc1 weights once (used in the last phase).
    for (int i = tid; i < 96; i += blockDim.x) smem[i] = Wb1[i];
    for (int i = tid; i < 64; i += blockDim.x) smem[1184 + i] = Wi1[i];
    for (int i = tid; i < 32; i += blockDim.x) {
        smem[96 + i] = bb1[i];   smem[1152 + i] = bb2[i];
        smem[1248 + i] = bi1[i]; smem[2304 + i] = bi2[i];
    }
    for (int i = tid; i < 1024; i += blockDim.x) {
        smem[128 + i] = Wb2[i];
        smem[1280 + i] = Wi2[i];
        smem[2336 + i] = Wc1[i];
    }
    __syncthreads();

    // ===== Phase A: degree count + per-edge bucket rank (4 edges/thread) ====
    for (int e4 = gid * 4; e4 < EE; e4 += stride * 4) {
        int4 d = *(const int4*)(dst + e4);
        int r0 = atomicAdd(&g_deg[d.x], 1);
        int r1 = atomicAdd(&g_deg[d.y], 1);
        int r2 = atomicAdd(&g_deg[d.z], 1);
        int r3 = atomicAdd(&g_deg[d.w], 1);
        *(int4*)(g_rank + e4) = make_int4(r0, r1, r2, r3);
    }
    gsync();

    // ===== Phase B: dinv + tile-local exclusive scan (1024-node tiles) ======
    for (int tile = blockIdx.x; tile < NTILE; tile += gridDim.x) {
        int base = tile * 1024 + tid * 4;
        int v[4];
#pragma unroll
        for (int r = 0; r < 4; r++) {
            int i = base + r;
            v[r] = (i < NN) ? g_deg[i] : 0;
            if (i < NN) g_dinv[i] = rsqrtf((float)(v[r] + 1));
        }
        int ts = v[0] + v[1] + v[2] + v[3];
        sInt[tid] = ts;
        __syncthreads();
#pragma unroll
        for (int d = 1; d < 256; d <<= 1) {
            int t2 = (tid >= d) ? sInt[tid - d] : 0;
            __syncthreads();
            sInt[tid] += t2;
            __syncthreads();
        }
        int run = sInt[tid] - ts;
#pragma unroll
        for (int r = 0; r < 4; r++) {
            if (base + r < NN) g_rowptr[base + r] = run;
            run += v[r];
        }
        if (tid == 255) g_blocksums[tile] = sInt[255];
        __syncthreads();
    }
    gsync();

    // ===== Phase C: every block rescans the 98 tile sums; finalize rowptr,
    //       reset deg for the next call ===================================
    if (tid < 128) sInt[tid] = (tid < NTILE) ? g_blocksums[tid] : 0;
    __syncthreads();
#pragma unroll
    for (int d = 1; d < 128; d <<= 1) {
        int t2 = (tid < 128 && tid >= d) ? sInt[tid - d] : 0;
        __syncthreads();
        if (tid < 128) sInt[tid] += t2;
        __syncthreads();
    }
    for (int i = gid; i < NN; i += stride) {
        int tile = i >> 10;
        int off = (tile == 0) ? 0 : sInt[tile - 1];
        g_rowptr[i] = g_rowptr[i] + off;
        g_deg[i] = 0;
    }
    if (gid == 0) g_rowptr[NN] = EE;
    gsync();

    // ===== Phase D: atomic-free CSR fill (streaming) ========================
    for (int e4 = gid * 4; e4 < EE; e4 += stride * 4) {
        int4 s = *(const int4*)(src + e4);
        int4 d = *(const int4*)(dst + e4);
        int4 r = *(const int4*)(g_rank + e4);
        g_csri[__ldg(&g_rowptr[d.x]) + r.x] = s.x;
        g_csri[__ldg(&g_rowptr[d.y]) + r.y] = s.y;
        g_csri[__ldg(&g_rowptr[d.z]) + r.z] = s.z;
        g_csri[__ldg(&g_rowptr[d.w]) + r.w] = s.w;
    }

    // ===== Phase E: encoder + xform1 -> t0 (independent of D; no barrier) ===
    for (int j = gid; j < NN; j += stride) {
        bool bd = j < NB;
        int node = bd ? __ldg(&bidx[j]) : __ldg(&iidx[j - NB]);
        const float* W1 = bd ? smem : smem + 1184;
        const float* b1 = bd ? smem + 96 : smem + 1248;
        const float* W2 = bd ? smem + 128 : smem + 1280;
        const float* b2 = bd ? smem + 1152 : smem + 2304;
        float2 xv = __ldg((const float2*)x + node);
        float yv = bd ? __ldg(&y[node]) : 0.0f;

        float h[32];
#pragma unroll
        for (int tile = 0; tile < 4; tile++) {
            float acc[8];
#pragma unroll
            for (int jj = 0; jj < 8; jj++) acc[jj] = b2[tile * 8 + jj];
#pragma unroll 8
            for (int k = 0; k < 32; k++) {
                float a = xv.x * W1[k] + xv.y * W1[32 + k] + b1[k];
                if (bd) a += yv * W1[64 + k];
                a = fmaxf(a, 0.0f);
                const float* wrow = W2 + k * 32 + tile * 8;
#pragma unroll
                for (int jj = 0; jj < 8; jj++) acc[jj] += a * wrow[jj];
            }
#pragma unroll
            for (int jj = 0; jj < 8; jj++) h[tile * 8 + jj] = fmaxf(acc[jj], 0.0f);
        }

        float di = g_dinv[node];
        const float* sWc = smem + 2336;
        unsigned* tp = (unsigned*)&g_t0[node * HH];
#pragma unroll
        for (int tile = 0; tile < 4; tile++) {
            float acc[8];
#pragma unroll
            for (int jj = 0; jj < 8; jj++) acc[jj] = 0.0f;
#pragma unroll
            for (int k = 0; k < 32; k++) {
                float v = h[k];
                const float* wrow = sWc + k * 32 + tile * 8;
#pragma unroll
                for (int jj = 0; jj < 8; jj++) acc[jj] += v * wrow[jj];
            }
            tp[tile * 4 + 0] = pk(acc[0] * di, acc[1] * di);
            tp[tile * 4 + 1] = pk(acc[2] * di, acc[3] * di);
            tp[tile * 4 + 2] = pk(acc[4] * di, acc[5] * di);
            tp[tile * 4 + 3] = pk(acc[6] * di, acc[7] * di);
        }
    }
}

// ---------------------------------------------------------------------------
// Shared gather core: 4 lanes/node, lane sub owns 8 columns (uint4 row load).
// Edge loop unrolled x8. Returns relu'd h chunk by value.
// ---------------------------------------------------------------------------
struct H8 { float4 a, b; };

__device__ __forceinline__ void addu4(float4& a, float4& b, uint4 u) {
    const __half2* hh = (const __half2*)&u;
    float2 f0 = __half22float2(hh[0]);
    float2 f1 = __half22float2(hh[1]);
    float2 f2 = __half22float2(hh[2]);
    float2 f3 = __half22float2(hh[3]);
    a.x += f0.x; a.y += f0.y; a.z += f1.x; a.w += f1.y;
    b.x += f2.x; b.y += f2.y; b.z += f3.x; b.w += f3.y;
}

__device__ __forceinline__ H8 gather_core(const __half* __restrict__ tin,
                                          const float* __restrict__ bvec,
                                          int node, int sub) {
    const uint4* tp = (const uint4*)tin;
    float4 aA0 = make_float4(0.f, 0.f, 0.f, 0.f), aA1 = aA0;
    float4 aB0 = aA0, aB1 = aA0;
    addu4(aA0, aA1, __ldg(tp + node * 4 + sub));        // self term
    int e = __ldg(&g_rowptr[node]);
    int e1 = __ldg(&g_rowptr[node + 1]);
    for (; e + 7 < e1; e += 8) {
        int s0 = __ldg(&g_csri[e + 0]);
        int s1 = __ldg(&g_csri[e + 1]);
        int s2 = __ldg(&g_csri[e + 2]);
        int s3 = __ldg(&g_csri[e + 3]);
        int s4 = __ldg(&g_csri[e + 4]);
        int s5 = __ldg(&g_csri[e + 5]);
        int s6 = __ldg(&g_csri[e + 6]);
        int s7 = __ldg(&g_csri[e + 7]);
        uint4 u0 = __ldg(tp + s0 * 4 + sub);
        uint4 u1 = __ldg(tp + s1 * 4 + sub);
        uint4 u2 = __ldg(tp + s2 * 4 + sub);
        uint4 u3 = __ldg(tp + s3 * 4 + sub);
        uint4 u4 = __ldg(tp + s4 * 4 + sub);
        uint4 u5 = __ldg(tp + s5 * 4 + sub);
        uint4 u6 = __ldg(tp + s6 * 4 + sub);
        uint4 u7 = __ldg(tp + s7 * 4 + sub);
        addu4(aA0, aA1, u0);
        addu4(aB0, aB1, u1);
        addu4(aA0, aA1, u2);
        addu4(aB0, aB1, u3);
        addu4(aA0, aA1, u4);
        addu4(aB0, aB1, u5);
        addu4(aA0, aA1, u6);
        addu4(aB0, aB1, u7);
    }
    for (; e + 3 < e1; e += 4) {
        int s0 = __ldg(&g_csri[e + 0]);
        int s1 = __ldg(&g_csri[e + 1]);
        int s2 = __ldg(&g_csri[e + 2]);
        int s3 = __ldg(&g_csri[e + 3]);
        uint4 u0 = __ldg(tp + s0 * 4 + sub);
        uint4 u1 = __ldg(tp + s1 * 4 + sub);
        uint4 u2 = __ldg(tp + s2 * 4 + sub);
        uint4 u3 = __ldg(tp + s3 * 4 + sub);
        addu4(aA0, aA1, u0);
        addu4(aB0, aB1, u1);
        addu4(aA0, aA1, u2);
        addu4(aB0, aB1, u3);
    }
    for (; e < e1; e++)
        addu4(aA0, aA1, __ldg(tp + __ldg(&g_csri[e]) * 4 + sub));

    float di = g_dinv[node];
    const float4* bp = (const float4*)bvec;
    float4 b0 = __ldg(bp + sub * 2 + 0);
    float4 b1 = __ldg(bp + sub * 2 + 1);
    H8 h;
    h.a.x = fmaxf(b0.x + di * (aA0.x + aB0.x), 0.0f);
    h.a.y = fmaxf(b0.y + di * (aA0.y + aB0.y), 0.0f);
    h.a.z = fmaxf(b0.z + di * (aA0.z + aB0.z), 0.0f);
    h.a.w = fmaxf(b0.w + di * (aA0.w + aB0.w), 0.0f);
    h.b.x = fmaxf(b1.x + di * (aA1.x + aB1.x), 0.0f);
    h.b.y = fmaxf(b1.y + di * (aA1.y + aB1.y), 0.0f);
    h.b.z = fmaxf(b1.z + di * (aA1.z + aB1.z), 0.0f);
    h.b.w = fmaxf(b1.w + di * (aA1.w + aB1.w), 0.0f);
    return h;
}

// ---------------------------------------------------------------------------
// Gather + next-layer xform fused (quad shuffles assemble full 32-dim h).
// ---------------------------------------------------------------------------
#define XSTEP(comp, ridx)                                                    \
    {                                                                        \
        float hv = __shfl_sync(0xFFFFFFFFu, (comp), q, 4);                   \
        const float* w = sW + (q * 8 + (ridx)) * 32 + sub * 8;               \
        a0 += hv * w[0]; a1 += hv * w[1]; a2 += hv * w[2]; a3 += hv * w[3];  \
        a4 += hv * w[4]; a5 += hv * w[5]; a6 += hv * w[6]; a7 += hv * w[7];  \
    }

__global__ void gx_kernel(int in_sel, int out_sel,
                          const float* __restrict__ bvec, const float* __restrict__ Wnext) {
    __shared__ float sW[1024];
    for (int i = threadIdx.x; i < 1024; i += blockDim.x) sW[i] = Wnext[i];
    __syncthreads();

    const __half* tin = tbuf(in_sel);
    __half* tout = tbuf(out_sel);

    int gid = blockIdx.x * blockDim.x + threadIdx.x;
    int node = gid >> 2, sub = gid & 3;
    if (node >= NN) node = NN - 1;          // clamp; duplicate quads write same data

    H8 h = gather_core(tin, bvec, node, sub);

    float di = g_dinv[node];
    float a0 = 0.f, a1 = 0.f, a2 = 0.f, a3 = 0.f;
    float a4 = 0.f, a5 = 0.f, a6 = 0.f, a7 = 0.f;
#pragma unroll
    for (int q = 0; q < 4; q++) {
        XSTEP(h.a.x, 0) XSTEP(h.a.y, 1) XSTEP(h.a.z, 2) XSTEP(h.a.w, 3)
        XSTEP(h.b.x, 4) XSTEP(h.b.y, 5) XSTEP(h.b.z, 6) XSTEP(h.b.w, 7)
    }
    uint4 o;
    o.x = pk(a0 * di, a1 * di);
    o.y = pk(a2 * di, a3 * di);
    o.z = pk(a4 * di, a5 * di);
    o.w = pk(a6 * di, a7 * di);
    ((uint4*)tout)[node * 4 + sub] = o;
}

// ---------------------------------------------------------------------------
// Last gather + head fused: out[node] = dot(relu(h3), Wf) + bf via quad reduce.
// ---------------------------------------------------------------------------
__global__ void ghead_kernel(int in_sel, const float* __restrict__ bvec,
                             const float* __restrict__ Wf, const float* __restrict__ bf,
                             float* __restrict__ out) {
    const __half* tin = tbuf(in_sel);
    int gid = blockIdx.x * blockDim.x + threadIdx.x;
    int node = gid >> 2, sub = gid & 3;
    if (node >= NN) node = NN - 1;

    H8 h = gather_core(tin, bvec, node, sub);

    const float4* wp = (const float4*)Wf;
    float4 w0 = __ldg(wp + sub * 2 + 0);
    float4 w1 = __ldg(wp + sub * 2 + 1);
    float p = h.a.x * w0.x + h.a.y * w0.y + h.a.z * w0.z + h.a.w * w0.w +
              h.b.x * w1.x + h.b.y * w1.y + h.b.z * w1.z + h.b.w * w1.w;
    p += __shfl_xor_sync(0xFFFFFFFFu, p, 1, 4);
    p += __shfl_xor_sync(0xFFFFFFFFu, p, 2, 4);
    if (sub == 0) out[node] = p + __ldg(bf);
}

extern "C" void kernel_launch(void* const* d_in, const int* in_sizes, int n_in,
                              void* d_out, int out_size) {
    const float* x    = (const float*)d_in[0];
    const float* y    = (const float*)d_in[1];
    const int*   ei   = (const int*)d_in[2];
    const int*   bidx = (const int*)d_in[3];
    const int*   iidx = (const int*)d_in[4];
    const float* Wb1 = (const float*)d_in[5];
    const float* bb1 = (const float*)d_in[6];
    const float* Wb2 = (const float*)d_in[7];
    const float* bb2 = (const float*)d_in[8];
    const float* Wi1 = (const float*)d_in[9];
    const float* bi1 = (const float*)d_in[10];
    const float* Wi2 = (const float*)d_in[11];
    const float* bi2 = (const float*)d_in[12];
    const float* Wc1 = (const float*)d_in[13];
    const float* bc1 = (const float*)d_in[14];
    const float* Wc2 = (const float*)d_in[15];
    const float* bc2 = (const float*)d_in[16];
    const float* Wc3 = (const float*)d_in[17];
    const float* bc3 = (const float*)d_in[18];
    const float* Wf  = (const float*)d_in[19];
    const float* bf  = (const float*)d_in[20];

    int NB = in_sizes[3];
    const int* src = ei;        // edge_index[0,:]
    const int* dst = ei + EE;   // edge_index[1,:]

    // Exactly-resident grid for the persistent CSR+enc kernel's grid barrier.
    int dev = 0;
    cudaGetDevice(&dev);
    int sms = 148;
    cudaDeviceGetAttribute(&sms, cudaDevAttrMultiProcessorCount, dev);
    int per = 1;
    cudaOccupancyMaxActiveBlocksPerMultiprocessor(&per, csr_enc_kernel, 256, 0);
    if (per < 1) per = 1;
    int nblk = sms * per;

    // 1) CSR build + encoder + xform1 (persistent, 4 former launches in one)
    csr_enc_kernel<<<nblk, 256>>>(x, y, src, dst, bidx, iidx, NB,
                                  Wb1, bb1, Wb2, bb2, Wi1, bi1, Wi2, bi2, Wc1);

    // 2-4) Conv gathers (full occupancy; latency/bandwidth-critical)
    gx_kernel<<<CDIV(NN * 4, 256), 256>>>(0, 1, bc1, Wc2);
    gx_kernel<<<CDIV(NN * 4, 256), 256>>>(1, 0, bc2, Wc3);
    ghead_kernel<<<CDIV(NN * 4, 256), 256>>>(0, bc3, Wf, bf, (float*)d_out);
}

// round 17
// speedup vs baseline: 1.0005x; 1.0005x over previous
#include <cuda_runtime.h>
#include <cuda_bf16.h>
#include <cuda_fp16.h>

// Problem constants (fixed by the dataset)
#define NN 100000
#define EE 1600000
#define HH 32
#define NTILE 98                       // ceil(NN / 1024)

#define CDIV(a, b) (((a) + (b) - 1) / (b))

// Scratch (static device globals; no allocation allowed)
__device__ int      g_deg[NN];         // zero at entry (reset each call in phase C)
__device__ int      g_rank[EE];        // within-dst-bucket rank of each edge
__device__ int      g_rowptr[NN + 1];
__device__ int      g_blocksums[NTILE];
__device__ float    g_dinv[NN];
__device__ int      g_csri[EE];        // src indices, bucketed by dst
__device__ __half   g_t0[NN * HH];     // t ping (fp16, pre-scaled by dinv[src])
__device__ __half   g_t1[NN * HH];     // t pong
__device__ unsigned g_bar_arrive;      // grid barrier state
__device__ unsigned g_bar_gen;

// Device-side buffer selection (NEVER pass __device__ globals from host!)
__device__ __forceinline__ __half* tbuf(int s) { return s ? g_t1 : g_t0; }

// ---------------------------------------------------------------------------
// Software grid barrier (all blocks resident by construction).
// ---------------------------------------------------------------------------
__device__ __forceinline__ void gsync() {
    __threadfence();
    __syncthreads();
    if (threadIdx.x == 0) {
        unsigned gen = *(volatile unsigned*)&g_bar_gen;
        unsigned rank = atomicAdd(&g_bar_arrive, 1u);
        if (rank == gridDim.x - 1) {
            g_bar_arrive = 0;
            __threadfence();
            atomicExch(&g_bar_gen, gen + 1u);
        } else {
            while (*(volatile unsigned*)&g_bar_gen == gen) { __nanosleep(64); }
        }
    }
    __syncthreads();
    __threadfence();
}

// Pack two floats into one fp16x2 word (scalar reinterpret; stays in regs).
__device__ __forceinline__ unsigned pk(float x, float y) {
    __half2 h = __float22half2_rn(make_float2(x, y));
    return *reinterpret_cast<unsigned*>(&h);
}

// ---------------------------------------------------------------------------
// Persistent kernel: CSR build (deg+rank -> tile scan -> finalize -> fill)
// and encoder+xform1 (fill/enc phases overlapped; disjoint outputs).
// smem: [0:3360) encoder weights (persist), [3360:3616) scan scratch.
// ---------------------------------------------------------------------------
__global__ void csr_enc_kernel(const float* __restrict__ x, const float* __restrict__ y,
                               const int* __restrict__ src, const int* __restrict__ dst,
                               const int* __restrict__ bidx, const int* __restrict__ iidx,
                               int NB,
                               const float* __restrict__ Wb1, const float* __restrict__ bb1,
                               const float* __restrict__ Wb2, const float* __restrict__ bb2,
                               const float* __restrict__ Wi1, const float* __restrict__ bi1,
                               const float* __restrict__ Wi2, const float* __restrict__ bi2,
                               const float* __restrict__ Wc1) {
    __shared__ float smem[3616];
    int* sInt = (int*)(smem + 3360);
    int tid = threadIdx.x;
    int gid = blockIdx.x * blockDim.x + tid;
    int stride = gridDim.x * blockDim.x;

    for (int i = tid; i < 96; i += blockDim.x) smem[i] = Wb1[i];
    for (int i = tid; i < 64; i += blockDim.x) smem[1184 + i] = Wi1[i];
    for (int i = tid; i < 32; i += blockDim.x) {
        smem[96 + i] = bb1[i];   smem[1152 + i] = bb2[i];
        smem[1248 + i] = bi1[i]; smem[2304 + i] = bi2[i];
    }
    for (int i = tid; i < 1024; i += blockDim.x) {
        smem[128 + i] = Wb2[i];
        smem[1280 + i] = Wi2[i];
        smem[2336 + i] = Wc1[i];
    }
    __syncthreads();

    // ===== Phase A: degree count + per-edge bucket rank (4 edges/thread) ====
    for (int e4 = gid * 4; e4 < EE; e4 += stride * 4) {
        int4 d = *(const int4*)(dst + e4);
        int r0 = atomicAdd(&g_deg[d.x], 1);
        int r1 = atomicAdd(&g_deg[d.y], 1);
        int r2 = atomicAdd(&g_deg[d.z], 1);
        int r3 = atomicAdd(&g_deg[d.w], 1);
        *(int4*)(g_rank + e4) = make_int4(r0, r1, r2, r3);
    }
    gsync();

    // ===== Phase B: dinv + tile-local exclusive scan (1024-node tiles) ======
    for (int tile = blockIdx.x; tile < NTILE; tile += gridDim.x) {
        int base = tile * 1024 + tid * 4;
        int v[4];
#pragma unroll
        for (int r = 0; r < 4; r++) {
            int i = base + r;
            v[r] = (i < NN) ? g_deg[i] : 0;
            if (i < NN) g_dinv[i] = rsqrtf((float)(v[r] + 1));
        }
        int ts = v[0] + v[1] + v[2] + v[3];
        sInt[tid] = ts;
        __syncthreads();
#pragma unroll
        for (int d = 1; d < 256; d <<= 1) {
            int t2 = (tid >= d) ? sInt[tid - d] : 0;
            __syncthreads();
            sInt[tid] += t2;
            __syncthreads();
        }
        int run = sInt[tid] - ts;
#pragma unroll
        for (int r = 0; r < 4; r++) {
            if (base + r < NN) g_rowptr[base + r] = run;
            run += v[r];
        }
        if (tid == 255) g_blocksums[tile] = sInt[255];
        __syncthreads();
    }
    gsync();

    // ===== Phase C: finalize rowptr; reset deg =============================
    if (tid < 128) sInt[tid] = (tid < NTILE) ? g_blocksums[tid] : 0;
    __syncthreads();
#pragma unroll
    for (int d = 1; d < 128; d <<= 1) {
        int t2 = (tid < 128 && tid >= d) ? sInt[tid - d] : 0;
        __syncthreads();
        if (tid < 128) sInt[tid] += t2;
        __syncthreads();
    }
    for (int i = gid; i < NN; i += stride) {
        int tile = i >> 10;
        int off = (tile == 0) ? 0 : sInt[tile - 1];
        g_rowptr[i] = g_rowptr[i] + off;
        g_deg[i] = 0;
    }
    if (gid == 0) g_rowptr[NN] = EE;
    gsync();

    // ===== Phase D: atomic-free CSR fill (streaming) ========================
    for (int e4 = gid * 4; e4 < EE; e4 += stride * 4) {
        int4 s = *(const int4*)(src + e4);
        int4 d = *(const int4*)(dst + e4);
        int4 r = *(const int4*)(g_rank + e4);
        g_csri[__ldg(&g_rowptr[d.x]) + r.x] = s.x;
        g_csri[__ldg(&g_rowptr[d.y]) + r.y] = s.y;
        g_csri[__ldg(&g_rowptr[d.z]) + r.z] = s.z;
        g_csri[__ldg(&g_rowptr[d.w]) + r.w] = s.w;
    }

    // ===== Phase E: encoder + xform1 -> t0 (independent of D) ===============
    for (int j = gid; j < NN; j += stride) {
        bool bd = j < NB;
        int node = bd ? __ldg(&bidx[j]) : __ldg(&iidx[j - NB]);
        const float* W1 = bd ? smem : smem + 1184;
        const float* b1 = bd ? smem + 96 : smem + 1248;
        const float* W2 = bd ? smem + 128 : smem + 1280;
        const float* b2 = bd ? smem + 1152 : smem + 2304;
        float2 xv = __ldg((const float2*)x + node);
        float yv = bd ? __ldg(&y[node]) : 0.0f;

        float h[32];
#pragma unroll
        for (int tile = 0; tile < 4; tile++) {
            float acc[8];
#pragma unroll
            for (int jj = 0; jj < 8; jj++) acc[jj] = b2[tile * 8 + jj];
#pragma unroll 8
            for (int k = 0; k < 32; k++) {
                float a = xv.x * W1[k] + xv.y * W1[32 + k] + b1[k];
                if (bd) a += yv * W1[64 + k];
                a = fmaxf(a, 0.0f);
                const float* wrow = W2 + k * 32 + tile * 8;
#pragma unroll
                for (int jj = 0; jj < 8; jj++) acc[jj] += a * wrow[jj];
            }
#pragma unroll
            for (int jj = 0; jj < 8; jj++) h[tile * 8 + jj] = fmaxf(acc[jj], 0.0f);
        }

        float di = g_dinv[node];
        const float* sWc = smem + 2336;
        unsigned* tp = (unsigned*)&g_t0[node * HH];
#pragma unroll
        for (int tile = 0; tile < 4; tile++) {
            float acc[8];
#pragma unroll
            for (int jj = 0; jj < 8; jj++) acc[jj] = 0.0f;
#pragma unroll
            for (int k = 0; k < 32; k++) {
                float v = h[k];
                const float* wrow = sWc + k * 32 + tile * 8;
#pragma unroll
                for (int jj = 0; jj < 8; jj++) acc[jj] += v * wrow[jj];
            }
            tp[tile * 4 + 0] = pk(acc[0] * di, acc[1] * di);
            tp[tile * 4 + 1] = pk(acc[2] * di, acc[3] * di);
            tp[tile * 4 + 2] = pk(acc[4] * di, acc[5] * di);
            tp[tile * 4 + 3] = pk(acc[6] * di, acc[7] * di);
        }
    }
}

// ---------------------------------------------------------------------------
// Gather core: 4 lanes/node, lane sub owns 8 columns (uint4 row load).
// Instruction-lean inner loop: rows combined PAIRWISE in fp16 (1 HADD2 per
// half2 word) before one convert+fp32-accumulate per pair — 20 arith instr
// per 2 edges instead of 32. One extra fp16 rounding per pair (~5e-4 rel,
// random sign) on top of existing storage rounding.
// ---------------------------------------------------------------------------
struct H8 { float4 a, b; };

__device__ __forceinline__ void addu4(float4& a, float4& b, uint4 u) {
    const __half2* hh = (const __half2*)&u;
    float2 f0 = __half22float2(hh[0]);
    float2 f1 = __half22float2(hh[1]);
    float2 f2 = __half22float2(hh[2]);
    float2 f3 = __half22float2(hh[3]);
    a.x += f0.x; a.y += f0.y; a.z += f1.x; a.w += f1.y;
    b.x += f2.x; b.y += f2.y; b.z += f3.x; b.w += f3.y;
}

// Pairwise: acc += float(u + v) with the inner add done in fp16 (HADD2).
__device__ __forceinline__ void addp(float4& a, float4& b, uint4 u, uint4 v) {
    const __half2* hu = (const __half2*)&u;
    const __half2* hv = (const __half2*)&v;
    __half2 s0 = __hadd2(hu[0], hv[0]);
    __half2 s1 = __hadd2(hu[1], hv[1]);
    __half2 s2 = __hadd2(hu[2], hv[2]);
    __half2 s3 = __hadd2(hu[3], hv[3]);
    float2 f0 = __half22float2(s0);
    float2 f1 = __half22float2(s1);
    float2 f2 = __half22float2(s2);
    float2 f3 = __half22float2(s3);
    a.x += f0.x; a.y += f0.y; a.z += f1.x; a.w += f1.y;
    b.x += f2.x; b.y += f2.y; b.z += f3.x; b.w += f3.y;
}

__device__ __forceinline__ H8 gather_core(const __half* __restrict__ tin,
                                          const float* __restrict__ bvec,
                                          int node, int sub) {
    const uint4* tp = (const uint4*)tin;
    float4 aA0 = make_float4(0.f, 0.f, 0.f, 0.f), aA1 = aA0;
    float4 aB0 = aA0, aB1 = aA0;
    addu4(aA0, aA1, __ldg(tp + node * 4 + sub));        // self term
    int e = __ldg(&g_rowptr[node]);
    int e1 = __ldg(&g_rowptr[node + 1]);
    for (; e + 7 < e1; e += 8) {
        int s0 = __ldg(&g_csri[e + 0]);
        int s1 = __ldg(&g_csri[e + 1]);
        int s2 = __ldg(&g_csri[e + 2]);
        int s3 = __ldg(&g_csri[e + 3]);
        int s4 = __ldg(&g_csri[e + 4]);
        int s5 = __ldg(&g_csri[e + 5]);
        int s6 = __ldg(&g_csri[e + 6]);
        int s7 = __ldg(&g_csri[e + 7]);
        uint4 u0 = __ldg(tp + s0 * 4 + sub);
        uint4 u1 = __ldg(tp + s1 * 4 + sub);
        uint4 u2 = __ldg(tp + s2 * 4 + sub);
        uint4 u3 = __ldg(tp + s3 * 4 + sub);
        uint4 u4 = __ldg(tp + s4 * 4 + sub);
        uint4 u5 = __ldg(tp + s5 * 4 + sub);
        uint4 u6 = __ldg(tp + s6 * 4 + sub);
        uint4 u7 = __ldg(tp + s7 * 4 + sub);
        addp(aA0, aA1, u0, u1);
        addp(aB0, aB1, u2, u3);
        addp(aA0, aA1, u4, u5);
        addp(aB0, aB1, u6, u7);
    }
    for (; e + 3 < e1; e += 4) {
        int s0 = __ldg(&g_csri[e + 0]);
        int s1 = __ldg(&g_csri[e + 1]);
        int s2 = __ldg(&g_csri[e + 2]);
        int s3 = __ldg(&g_csri[e + 3]);
        uint4 u0 = __ldg(tp + s0 * 4 + sub);
        uint4 u1 = __ldg(tp + s1 * 4 + sub);
        uint4 u2 = __ldg(tp + s2 * 4 + sub);
        uint4 u3 = __ldg(tp + s3 * 4 + sub);
        addp(aA0, aA1, u0, u1);
        addp(aB0, aB1, u2, u3);
    }
    for (; e < e1; e++)
        addu4(aA0, aA1, __ldg(tp + __ldg(&g_csri[e]) * 4 + sub));

    float di = g_dinv[node];
    const float4* bp = (const float4*)bvec;
    float4 b0 = __ldg(bp + sub * 2 + 0);
    float4 b1 = __ldg(bp + sub * 2 + 1);
    H8 h;
    h.a.x = fmaxf(b0.x + di * (aA0.x + aB0.x), 0.0f);
    h.a.y = fmaxf(b0.y + di * (aA0.y + aB0.y), 0.0f);
    h.a.z = fmaxf(b0.z + di * (aA0.z + aB0.z), 0.0f);
    h.a.w = fmaxf(b0.w + di * (aA0.w + aB0.w), 0.0f);
    h.b.x = fmaxf(b1.x + di * (aA1.x + aB1.x), 0.0f);
    h.b.y = fmaxf(b1.y + di * (aA1.y + aB1.y), 0.0f);
    h.b.z = fmaxf(b1.z + di * (aA1.z + aB1.z), 0.0f);
    h.b.w = fmaxf(b1.w + di * (aA1.w + aB1.w), 0.0f);
    return h;
}

// ---------------------------------------------------------------------------
// Gather + next-layer xform fused (quad shuffles assemble full 32-dim h).
// ---------------------------------------------------------------------------
#define XSTEP(comp, ridx)                                                    \
    {                                                                        \
        float hv = __shfl_sync(0xFFFFFFFFu, (comp), q, 4);                   \
        const float* w = sW + (q * 8 + (ridx)) * 32 + sub * 8;               \
        a0 += hv * w[0]; a1 += hv * w[1]; a2 += hv * w[2]; a3 += hv * w[3];  \
        a4 += hv * w[4]; a5 += hv * w[5]; a6 += hv * w[6]; a7 += hv * w[7];  \
    }

__global__ void gx_kernel(int in_sel, int out_sel,
                          const float* __restrict__ bvec, const float* __restrict__ Wnext) {
    __shared__ float sW[1024];
    for (int i = threadIdx.x; i < 1024; i += blockDim.x) sW[i] = Wnext[i];
    __syncthreads();

    const __half* tin = tbuf(in_sel);
    __half* tout = tbuf(out_sel);

    int gid = blockIdx.x * blockDim.x + threadIdx.x;
    int node = gid >> 2, sub = gid & 3;
    if (node >= NN) node = NN - 1;          // clamp; duplicate quads write same data

    H8 h = gather_core(tin, bvec, node, sub);

    float di = g_dinv[node];
    float a0 = 0.f, a1 = 0.f, a2 = 0.f, a3 = 0.f;
    float a4 = 0.f, a5 = 0.f, a6 = 0.f, a7 = 0.f;
#pragma unroll
    for (int q = 0; q < 4; q++) {
        XSTEP(h.a.x, 0) XSTEP(h.a.y, 1) XSTEP(h.a.z, 2) XSTEP(h.a.w, 3)
        XSTEP(h.b.x, 4) XSTEP(h.b.y, 5) XSTEP(h.b.z, 6) XSTEP(h.b.w, 7)
    }
    uint4 o;
    o.x = pk(a0 * di, a1 * di);
    o.y = pk(a2 * di, a3 * di);
    o.z = pk(a4 * di, a5 * di);
    o.w = pk(a6 * di, a7 * di);
    ((uint4*)tout)[node * 4 + sub] = o;
}

// ---------------------------------------------------------------------------
// Last gather + head fused: out[node] = dot(relu(h3), Wf) + bf via quad reduce.
// ---------------------------------------------------------------------------
__global__ void ghead_kernel(int in_sel, const float* __restrict__ bvec,
                             const float* __restrict__ Wf, const float* __restrict__ bf,
                             float* __restrict__ out) {
    const __half* tin = tbuf(in_sel);
    int gid = blockIdx.x * blockDim.x + threadIdx.x;
    int node = gid >> 2, sub = gid & 3;
    if (node >= NN) node = NN - 1;

    H8 h = gather_core(tin, bvec, node, sub);

    const float4* wp = (const float4*)Wf;
    float4 w0 = __ldg(wp + sub * 2 + 0);
    float4 w1 = __ldg(wp + sub * 2 + 1);
    float p = h.a.x * w0.x + h.a.y * w0.y + h.a.z * w0.z + h.a.w * w0.w +
              h.b.x * w1.x + h.b.y * w1.y + h.b.z * w1.z + h.b.w * w1.w;
    p += __shfl_xor_sync(0xFFFFFFFFu, p, 1, 4);
    p += __shfl_xor_sync(0xFFFFFFFFu, p, 2, 4);
    if (sub == 0) out[node] = p + __ldg(bf);
}

extern "C" void kernel_launch(void* const* d_in, const int* in_sizes, int n_in,
                              void* d_out, int out_size) {
    const float* x    = (const float*)d_in[0];
    const float* y    = (const float*)d_in[1];
    const int*   ei   = (const int*)d_in[2];
    const int*   bidx = (const int*)d_in[3];
    const int*   iidx = (const int*)d_in[4];
    const float* Wb1 = (const float*)d_in[5];
    const float* bb1 = (const float*)d_in[6];
    const float* Wb2 = (const float*)d_in[7];
    const float* bb2 = (const float*)d_in[8];
    const float* Wi1 = (const float*)d_in[9];
    const float* bi1 = (const float*)d_in[10];
    const float* Wi2 = (const float*)d_in[11];
    const float* bi2 = (const float*)d_in[12];
    const float* Wc1 = (const float*)d_in[13];
    const float* bc1 = (const float*)d_in[14];
    const float* Wc2 = (const float*)d_in[15];
    const float* bc2 = (const float*)d_in[16];
    const float* Wc3 = (const float*)d_in[17];
    const float* bc3 = (const float*)d_in[18];
    const float* Wf  = (const float*)d_in[19];
    const float* bf  = (const float*)d_in[20];

    int NB = in_sizes[3];
    const int* src = ei;        // edge_index[0,:]
    const int* dst = ei + EE;   // edge_index[1,:]

    // Exactly-resident grid for the persistent CSR+enc kernel's grid barrier.
    int dev = 0;
    cudaGetDevice(&dev);
    int sms = 148;
    cudaDeviceGetAttribute(&sms, cudaDevAttrMultiProcessorCount, dev);
    int per = 1;
    cudaOccupancyMaxActiveBlocksPerMultiprocessor(&per, csr_enc_kernel, 256, 0);
    if (per < 1) per = 1;
    int nblk = sms * per;

    // 1) CSR build + encoder + xform1 (persistent)
    csr_enc_kernel<<<nblk, 256>>>(x, y, src, dst, bidx, iidx, NB,
                                  Wb1, bb1, Wb2, bb2, Wi1, bi1, Wi2, bi2, Wc1);

    // 2-4) Conv gathers (full occupancy)
    gx_kernel<<<CDIV(NN * 4, 256), 256>>>(0, 1, bc1, Wc2);
    gx_kernel<<<CDIV(NN * 4, 256), 256>>>(1, 0, bc2, Wc3);
    ghead_kernel<<<CDIV(NN * 4, 256), 256>>>(0, bc3, Wf, bf, (float*)d_out);
}